// round 5
// baseline (speedup 1.0000x reference)
#include <cuda_runtime.h>

// Sliding-window (no-overlap chunk) attention, fp32 with packed f32x2 FMA.
// B=4, S=8192, H=16, D=64, window w=128, C=64 chunks.
// Outputs: out [B,S,H,64] then attn [B,S,H,384] concatenated in d_out.

constexpr int Bc = 4;
constexpr int Sc = 8192;
constexpr int Hc = 16;
constexpr int Dc = 64;
constexpr int Wn = 128;          // window / chunk size
constexpr int Cc = Sc / Wn;      // 64 chunks
constexpr int QT = 32;           // queries per block
constexpr int NT = 256;          // threads per block
constexpr int PRS = 384;         // score row stride (floats)

// smem layout (floats)
constexpr int OFF_Q  = 0;                  // Qs2[64][32] duplicated pairs (d-major) = 4096 floats
constexpr int OFF_KV = 4096;               // Ks[64][128] transposed OR Vs[128][64] = 8192 floats
constexpr int OFF_P  = 4096 + 8192;        // Ps[32][384]
constexpr int SMEM_FLOATS = OFF_P + QT * PRS;   // 24576 floats = 96 KB

using ull = unsigned long long;

__device__ __forceinline__ void ffma2(ull& d, ull a, ull b) {
    asm("fma.rn.f32x2 %0, %1, %2, %0;" : "+l"(d) : "l"(a), "l"(b));
}
__device__ __forceinline__ ull dup2(float v) {
    ull r; asm("mov.b64 %0, {%1, %1};" : "=l"(r) : "f"(v)); return r;
}
__device__ __forceinline__ float2 u2f(ull v) {
    float2 f; asm("mov.b64 {%0, %1}, %2;" : "=f"(f.x), "=f"(f.y) : "l"(v)); return f;
}

__global__ __launch_bounds__(NT, 2)
void swa_noovl_kernel(const float* __restrict__ q,
                      const float* __restrict__ k,
                      const float* __restrict__ v,
                      float* __restrict__ out,
                      float* __restrict__ attn)
{
    extern __shared__ float sm[];
    float* Qs = sm + OFF_Q;      // duplicated-pair layout: row d has 64 floats (32 pairs)
    float* KV = sm + OFF_KV;
    float* Ps = sm + OFF_P;

    const int tid = threadIdx.x;
    const int c   = blockIdx.x >> 2;        // chunk
    const int qt  = blockIdx.x & 3;         // query sub-tile within chunk
    const int h   = blockIdx.y;
    const int b   = blockIdx.z;
    const int s0  = c * Wn + qt * QT;

    const size_t rowstride = (size_t)Hc * Dc;   // 1024 floats between seq positions

    // ---- Load Q tile transposed+duplicated: Qs2[d][y] = {q, q} ----
    {
        const float* qbase = q + ((size_t)b * Sc + s0) * rowstride + (size_t)h * Dc;
        int f = tid;
        #pragma unroll
        for (int i = 0; i < 2; i++) {          // 512 float4 total
            const int y = f & 31;
            const int g = f >> 5;              // dgroup 0..15
            const float4 val = *(const float4*)(qbase + (size_t)y * rowstride + g * 4);
            *(float2*)(Qs + (4 * g + 0) * 64 + 2 * y) = make_float2(val.x, val.x);
            *(float2*)(Qs + (4 * g + 1) * 64 + 2 * y) = make_float2(val.y, val.y);
            *(float2*)(Qs + (4 * g + 2) * 64 + 2 * y) = make_float2(val.z, val.z);
            *(float2*)(Qs + (4 * g + 3) * 64 + 2 * y) = make_float2(val.w, val.w);
            f += NT;
        }
    }

    // ================= QK^T : scores into Ps (f32x2 packed) =================
    const int r0 = (tid >> 5) * 4;    // GEMM1: 8 row-groups of 4
    const int c0 = (tid & 31) * 4;    //        32 col-groups of 4

    for (int e = 0; e < 3; e++) {
        const int kc = c - 1 + e;
        const bool valid = (kc >= 0) && (kc < Cc);
        __syncthreads();   // previous GEMM done reading KV
        if (valid) {
            // load K chunk transposed: Ks[d][y]
            const float* kbase = k + ((size_t)b * Sc + (size_t)kc * Wn) * rowstride + (size_t)h * Dc;
            int f = tid;
            #pragma unroll
            for (int i = 0; i < 8; i++) {      // 2048 float4 total
                const int y = f & 127;
                const int g = f >> 7;          // dgroup 0..15
                const float4 val = *(const float4*)(kbase + (size_t)y * rowstride + g * 4);
                KV[(4 * g + 0) * Wn + y] = val.x;
                KV[(4 * g + 1) * Wn + y] = val.y;
                KV[(4 * g + 2) * Wn + y] = val.z;
                KV[(4 * g + 3) * Wn + y] = val.w;
                f += NT;
            }
        }
        __syncthreads();
        if (valid) {
            ull acc[4][2];
            #pragma unroll
            for (int i = 0; i < 4; i++) { acc[i][0] = 0ull; acc[i][1] = 0ull; }

            #pragma unroll 8
            for (int d = 0; d < Dc; d++) {
                const ull* Qp = (const ull*)(Qs + d * 64);    // 32 dup-pairs
                const ulonglong2 A01 = *(const ulonglong2*)(Qp + r0);      // rows r0, r0+1 (bcast)
                const ulonglong2 A23 = *(const ulonglong2*)(Qp + r0 + 2);  // rows r0+2, r0+3
                const ulonglong2 Bv  = *(const ulonglong2*)(KV + d * Wn + c0);
                ffma2(acc[0][0], A01.x, Bv.x); ffma2(acc[0][1], A01.x, Bv.y);
                ffma2(acc[1][0], A01.y, Bv.x); ffma2(acc[1][1], A01.y, Bv.y);
                ffma2(acc[2][0], A23.x, Bv.x); ffma2(acc[2][1], A23.x, Bv.y);
                ffma2(acc[3][0], A23.y, Bv.x); ffma2(acc[3][1], A23.y, Bv.y);
            }
            #pragma unroll
            for (int i = 0; i < 4; i++) {
                const float2 lo = u2f(acc[i][0]);
                const float2 hi = u2f(acc[i][1]);
                *(float4*)(Ps + (size_t)(r0 + i) * PRS + e * Wn + c0) =
                    make_float4(lo.x, lo.y, hi.x, hi.y);
            }
        } else {
            // padded neighbor: exact score 0 (matches reference zero-padding)
            const int r    = tid >> 3;
            const int col0 = (tid & 7) * 16;
            const float4 z = make_float4(0.f, 0.f, 0.f, 0.f);
            #pragma unroll
            for (int j = 0; j < 4; j++)
                *(float4*)(Ps + (size_t)r * PRS + e * Wn + col0 + 4 * j) = z;
        }
    }
    __syncthreads();

    // ================= softmax over 384 + write attn =================
    {
        const int lane = tid & 31;
        const int w    = tid >> 5;
        #pragma unroll
        for (int rr = 0; rr < 4; rr++) {
            const int r = w * 4 + rr;
            float* prow = Ps + (size_t)r * PRS;
            float4 vv[3];
            float m = -3.402823466e38f;
            #pragma unroll
            for (int kk = 0; kk < 3; kk++) {
                vv[kk] = *(const float4*)(prow + kk * Wn + lane * 4);
                m = fmaxf(m, fmaxf(fmaxf(vv[kk].x, vv[kk].y), fmaxf(vv[kk].z, vv[kk].w)));
            }
            #pragma unroll
            for (int o = 16; o; o >>= 1)
                m = fmaxf(m, __shfl_xor_sync(0xffffffffu, m, o));

            float ssum = 0.0f;
            #pragma unroll
            for (int kk = 0; kk < 3; kk++) {
                vv[kk].x = __expf(vv[kk].x - m);
                vv[kk].y = __expf(vv[kk].y - m);
                vv[kk].z = __expf(vv[kk].z - m);
                vv[kk].w = __expf(vv[kk].w - m);
                ssum += vv[kk].x + vv[kk].y + vv[kk].z + vv[kk].w;
            }
            #pragma unroll
            for (int o = 16; o; o >>= 1)
                ssum += __shfl_xor_sync(0xffffffffu, ssum, o);

            const float inv = 1.0f / ssum;
            float* arow = attn + (((size_t)b * Sc + (s0 + r)) * Hc + h) * (size_t)(3 * Wn);
            #pragma unroll
            for (int kk = 0; kk < 3; kk++) {
                vv[kk].x *= inv; vv[kk].y *= inv; vv[kk].z *= inv; vv[kk].w *= inv;
                *(float4*)(prow + kk * Wn + lane * 4) = vv[kk];       // keep normalized P
                *(float4*)(arow + kk * Wn + lane * 4) = vv[kk];       // coalesced output
            }
        }
    }

    // ================= P @ V_ext (f32x2 packed) =================
    ull acc2[2][2];
    acc2[0][0] = 0ull; acc2[0][1] = 0ull; acc2[1][0] = 0ull; acc2[1][1] = 0ull;

    const int r0b = (tid >> 4) * 2;   // 16 row-groups of 2
    const int c0b = (tid & 15) * 4;   // 16 col-groups of 4

    for (int e = 0; e < 3; e++) {
        const int kc = c - 1 + e;
        if (kc < 0 || kc >= Cc) continue;   // uniform across block
        __syncthreads();   // prior GEMM2 done reading KV; softmax writes to Ps visible
        // load V chunk natural: Vs[y][d]
        const float* vbase = v + ((size_t)b * Sc + (size_t)kc * Wn) * rowstride + (size_t)h * Dc;
        int f = tid;
        #pragma unroll
        for (int i = 0; i < 8; i++) {
            const int y = f >> 4;
            const int g = f & 15;
            *(float4*)(KV + (size_t)y * Dc + g * 4) =
                *(const float4*)(vbase + (size_t)y * rowstride + g * 4);
            f += NT;
        }
        __syncthreads();

        const float* p0 = Ps + (size_t)(r0b + 0) * PRS + e * Wn;
        const float* p1 = Ps + (size_t)(r0b + 1) * PRS + e * Wn;
        #pragma unroll 4
        for (int y = 0; y < Wn; y += 4) {
            const float4 p0v = *(const float4*)(p0 + y);
            const float4 p1v = *(const float4*)(p1 + y);
            {
                const ulonglong2 Bv = *(const ulonglong2*)(KV + (size_t)(y + 0) * Dc + c0b);
                const ull A0 = dup2(p0v.x), A1 = dup2(p1v.x);
                ffma2(acc2[0][0], A0, Bv.x); ffma2(acc2[0][1], A0, Bv.y);
                ffma2(acc2[1][0], A1, Bv.x); ffma2(acc2[1][1], A1, Bv.y);
            }
            {
                const ulonglong2 Bv = *(const ulonglong2*)(KV + (size_t)(y + 1) * Dc + c0b);
                const ull A0 = dup2(p0v.y), A1 = dup2(p1v.y);
                ffma2(acc2[0][0], A0, Bv.x); ffma2(acc2[0][1], A0, Bv.y);
                ffma2(acc2[1][0], A1, Bv.x); ffma2(acc2[1][1], A1, Bv.y);
            }
            {
                const ulonglong2 Bv = *(const ulonglong2*)(KV + (size_t)(y + 2) * Dc + c0b);
                const ull A0 = dup2(p0v.z), A1 = dup2(p1v.z);
                ffma2(acc2[0][0], A0, Bv.x); ffma2(acc2[0][1], A0, Bv.y);
                ffma2(acc2[1][0], A1, Bv.x); ffma2(acc2[1][1], A1, Bv.y);
            }
            {
                const ulonglong2 Bv = *(const ulonglong2*)(KV + (size_t)(y + 3) * Dc + c0b);
                const ull A0 = dup2(p0v.w), A1 = dup2(p1v.w);
                ffma2(acc2[0][0], A0, Bv.x); ffma2(acc2[0][1], A0, Bv.y);
                ffma2(acc2[1][0], A1, Bv.x); ffma2(acc2[1][1], A1, Bv.y);
            }
        }
    }

    // write out [B,S,H,64]
    {
        float* obase = out + ((size_t)b * Sc + s0) * rowstride + (size_t)h * Dc;
        #pragma unroll
        for (int i = 0; i < 2; i++) {
            const float2 lo = u2f(acc2[i][0]);
            const float2 hi = u2f(acc2[i][1]);
            *(float4*)(obase + (size_t)(r0b + i) * rowstride + c0b) =
                make_float4(lo.x, lo.y, hi.x, hi.y);
        }
    }
}

extern "C" void kernel_launch(void* const* d_in, const int* in_sizes, int n_in,
                              void* d_out, int out_size)
{
    const float* q = (const float*)d_in[0];
    const float* k = (const float*)d_in[1];
    const float* v = (const float*)d_in[2];
    float* out  = (float*)d_out;
    float* attn = out + (size_t)Bc * Sc * Hc * Dc;   // out first, then attn

    cudaFuncSetAttribute(swa_noovl_kernel,
                         cudaFuncAttributeMaxDynamicSharedMemorySize,
                         SMEM_FLOATS * (int)sizeof(float));

    dim3 grid(Cc * 4, Hc, Bc);   // (chunk*4 + qtile, head, batch)
    swa_noovl_kernel<<<grid, NT, SMEM_FLOATS * sizeof(float)>>>(q, k, v, out, attn);
}